// round 1
// baseline (speedup 1.0000x reference)
#include <cuda_runtime.h>
#include <math_constants.h>

#define B_  16
#define C_  256
#define IC_ 32
#define M_  16384
#define TM_ 128
#define TILES_ (M_/TM_)            // 128
#define RSQRT_IC 0.17677669529663687f

// ---------------- scratch (__device__ globals; no allocation allowed) -------
__device__ float d_g[(size_t)B_*IC_*M_];               // 33.5 MB  g_x (biased)
__device__ float d_partG[(size_t)B_*TILES_*IC_*IC_];   // 8.4 MB   per-tile t.t^T
__device__ float d_partS[(size_t)B_*TILES_*IC_];       //          per-tile sum(t)
__device__ float d_weff[(size_t)B_*IC_*C_];            //          w_w @ attn (transposed [j][c])

// ============================================================================
// Kernel 1: per (batch, 128-pixel tile): [theta;g](64x256) @ x(256x128)
//   - g rows (+bias) -> d_g
//   - t rows (+bias) -> smem -> partial Gram (32x32) + partial sums -> global
// ============================================================================
__global__ __launch_bounds__(256) void k1_proj(
    const float* __restrict__ x,
    const float* __restrict__ g_w, const float* __restrict__ g_b,
    const float* __restrict__ theta_w, const float* __restrict__ theta_b)
{
    __shared__ __align__(16) float Ws[64*64];   // weight chunk [r][c], row-major
    __shared__ __align__(16) float Xs[64*128];  // x chunk [cc][m]
    float* Ts = Xs;                             // reused after GEMM: t as [m][33]

    const int t    = threadIdx.x;
    const int tile = blockIdx.x;
    const int b    = blockIdx.y;
    const int mbase = tile * TM_;
    const int r0 = (t >> 5) * 8;                // 8 output rows / thread
    const int m0 = (t & 31) * 4;                // 4 pixels / thread

    float acc[8][4];
#pragma unroll
    for (int i = 0; i < 8; i++)
#pragma unroll
        for (int j = 0; j < 4; j++) acc[i][j] = 0.f;

    for (int c0 = 0; c0 < C_; c0 += 64) {
        // ---- load weight chunk: rows 0..31 = theta_w, 32..63 = g_w (coalesced)
#pragma unroll
        for (int k = 0; k < 16; k++) {
            int f = t + k * 256;                // 0..4095
            int r = f >> 6, c = f & 63;
            float w = (r < 32) ? theta_w[r * C_ + c0 + c]
                               : g_w[(r - 32) * C_ + c0 + c];
            Ws[r * 64 + c] = w;
        }
        // ---- load x chunk (coalesced float4 per row segment)
        const float* xb = x + ((size_t)b * C_ + c0) * M_ + mbase;
#pragma unroll
        for (int k = 0; k < 8; k++) {
            int f = t + k * 256;                // 0..2047 float4s
            int cc = f >> 5, m4 = (f & 31) * 4;
            *(float4*)(Xs + cc * 128 + m4) =
                *(const float4*)(xb + (size_t)cc * M_ + m4);
        }
        __syncthreads();

#pragma unroll 4
        for (int cc = 0; cc < 64; cc++) {
            float4 xv = *(const float4*)(Xs + cc * 128 + m0);   // conflict-free
#pragma unroll
            for (int ii = 0; ii < 8; ii++) {
                float w = Ws[(r0 + ii) * 64 + cc];              // warp broadcast
                acc[ii][0] += w * xv.x; acc[ii][1] += w * xv.y;
                acc[ii][2] += w * xv.z; acc[ii][3] += w * xv.w;
            }
        }
        __syncthreads();
    }

    // ---- epilogue: biases, route t -> smem, g -> global
    if (r0 < 32) {
#pragma unroll
        for (int ii = 0; ii < 8; ii++) {
            float bias = theta_b[r0 + ii];
#pragma unroll
            for (int mm = 0; mm < 4; mm++)
                Ts[(m0 + mm) * 33 + (r0 + ii)] = acc[ii][mm] + bias;
        }
    } else {
#pragma unroll
        for (int ii = 0; ii < 8; ii++) {
            int gr = r0 + ii - 32;
            float bias = g_b[gr];
            float4 v = make_float4(acc[ii][0] + bias, acc[ii][1] + bias,
                                   acc[ii][2] + bias, acc[ii][3] + bias);
            *(float4*)(d_g + ((size_t)b * IC_ + gr) * M_ + mbase + m0) = v;
        }
    }
    __syncthreads();

    // ---- partial Gram: warp w -> rows 4w..4w+3, lane j -> column j
    const int w = t >> 5, j = t & 31;
    float gac[4] = {0.f, 0.f, 0.f, 0.f};
    float sac = 0.f;
    for (int m = 0; m < TM_; m++) {
        float tj = Ts[m * 33 + j];              // contiguous, conflict-free
#pragma unroll
        for (int ii = 0; ii < 4; ii++)
            gac[ii] += Ts[m * 33 + w * 4 + ii] * tj;   // broadcast
        if (w == 0) sac += tj;
    }
    float* pG = d_partG + (size_t)(b * TILES_ + tile) * IC_ * IC_;
#pragma unroll
    for (int ii = 0; ii < 4; ii++)
        pG[(w * 4 + ii) * IC_ + j] = gac[ii];
    if (w == 0)
        d_partS[(size_t)(b * TILES_ + tile) * IC_ + j] = sac;
}

// ============================================================================
// Kernel 2 (one block per batch): reduce partials, sigma, softmax,
//   fold w_eff[j][c] = sum_i w_w[c][i]*attn[i][j]
// ============================================================================
__global__ __launch_bounds__(256) void k2_attn(const float* __restrict__ w_w)
{
    __shared__ float gram[IC_ * IC_];
    __shared__ float mu[IC_];
    __shared__ float attn[IC_ * IC_];
    const int t = threadIdx.x, b = blockIdx.x;

    for (int e = t; e < IC_ * IC_; e += 256) {
        float s = 0.f;
        const float* p = d_partG + (size_t)b * TILES_ * IC_ * IC_ + e;
        for (int tl = 0; tl < TILES_; tl++) s += p[(size_t)tl * IC_ * IC_];
        gram[e] = s;
    }
    if (t < IC_) {
        float s = 0.f;
        const float* p = d_partS + (size_t)b * TILES_ * IC_ + t;
        for (int tl = 0; tl < TILES_; tl++) s += p[tl * IC_];
        mu[t] = s * (1.0f / M_);
    }
    __syncthreads();

    if (t < IC_) {
        float row[IC_];
        float mx = -CUDART_INF_F;
#pragma unroll
        for (int jj = 0; jj < IC_; jj++) {
            float v = (gram[t * IC_ + jj] * (1.0f / M_) - mu[t] * mu[jj]) * RSQRT_IC;
            row[jj] = v; mx = fmaxf(mx, v);
        }
        float sum = 0.f;
#pragma unroll
        for (int jj = 0; jj < IC_; jj++) { row[jj] = __expf(row[jj] - mx); sum += row[jj]; }
        float inv = 1.0f / sum;
#pragma unroll
        for (int jj = 0; jj < IC_; jj++) attn[t * IC_ + jj] = row[jj] * inv;
    }
    __syncthreads();

    {   // thread t == channel c (256 threads, 256 channels)
        int c = t;
        float ww[IC_];
#pragma unroll
        for (int ii = 0; ii < IC_; ii++) ww[ii] = w_w[c * IC_ + ii];
#pragma unroll
        for (int jj = 0; jj < IC_; jj++) {
            float s = 0.f;
#pragma unroll
            for (int ii = 0; ii < IC_; ii++) s += ww[ii] * attn[ii * IC_ + jj];
            d_weff[((size_t)b * IC_ + jj) * C_ + c] = s;
        }
    }
}

// ============================================================================
// Kernel 3: out[b][c][m] = sum_j weff[j][c]*g[j][m] + w_b[c] + x[b][c][m]
//   block = (m-tile 128, c-block 64, batch); 8c x 4m register tile / thread
// ============================================================================
__global__ __launch_bounds__(256) void k3_out(
    const float* __restrict__ x, const float* __restrict__ w_b,
    float* __restrict__ out)
{
    __shared__ __align__(16) float gs[IC_ * 128];  // [j][m]
    __shared__ __align__(16) float wT[IC_ * 64];   // [j][c]

    const int t = threadIdx.x;
    const int tile = blockIdx.x, cb = blockIdx.y, b = blockIdx.z;
    const int mbase = tile * TM_;
    const int cbase = cb * 64;

#pragma unroll
    for (int k = 0; k < 4; k++) {                  // g tile: 1024 float4
        int f = t + k * 256;
        int i = f >> 5, m4 = (f & 31) * 4;
        *(float4*)(gs + i * 128 + m4) =
            *(const float4*)(d_g + ((size_t)b * IC_ + i) * M_ + mbase + m4);
    }
#pragma unroll
    for (int k = 0; k < 8; k++) {                  // weff tile: 2048 floats
        int f = t + k * 256;
        int i = f >> 6, c = f & 63;
        wT[i * 64 + c] = d_weff[((size_t)b * IC_ + i) * C_ + cbase + c];
    }
    __syncthreads();

    const int c0 = (t >> 5) * 8, m0 = (t & 31) * 4;
    float acc[8][4];
#pragma unroll
    for (int i = 0; i < 8; i++)
#pragma unroll
        for (int j = 0; j < 4; j++) acc[i][j] = 0.f;

#pragma unroll
    for (int i = 0; i < IC_; i++) {
        float4 gv = *(const float4*)(gs + i * 128 + m0);   // conflict-free
#pragma unroll
        for (int ii = 0; ii < 8; ii++) {
            float w = wT[i * 64 + c0 + ii];                // warp broadcast
            acc[ii][0] += w * gv.x; acc[ii][1] += w * gv.y;
            acc[ii][2] += w * gv.z; acc[ii][3] += w * gv.w;
        }
    }

    const size_t base = ((size_t)b * C_ + cbase + c0) * M_ + mbase + m0;
#pragma unroll
    for (int ii = 0; ii < 8; ii++) {
        float wb = w_b[cbase + c0 + ii];
        float4 xv = *(const float4*)(x + base + (size_t)ii * M_);
        float4 o = make_float4(acc[ii][0] + wb + xv.x, acc[ii][1] + wb + xv.y,
                               acc[ii][2] + wb + xv.z, acc[ii][3] + wb + xv.w);
        *(float4*)(out + base + (size_t)ii * M_) = o;
    }
}

// ============================================================================
extern "C" void kernel_launch(void* const* d_in, const int* in_sizes, int n_in,
                              void* d_out, int out_size)
{
    const float* x       = (const float*)d_in[0];
    const float* g_w     = (const float*)d_in[1];
    const float* g_b     = (const float*)d_in[2];
    const float* theta_w = (const float*)d_in[3];
    const float* theta_b = (const float*)d_in[4];
    const float* w_w     = (const float*)d_in[5];
    const float* w_b     = (const float*)d_in[6];
    float* out = (float*)d_out;

    k1_proj<<<dim3(TILES_, B_), 256>>>(x, g_w, g_b, theta_w, theta_b);
    k2_attn<<<B_, 256>>>(w_w);
    k3_out<<<dim3(TILES_, 4, B_), 256>>>(x, w_b, out);
}

// round 3
// speedup vs baseline: 1.2890x; 1.2890x over previous
#include <cuda_runtime.h>
#include <cuda_bf16.h>
#include <math_constants.h>
#include <cstdint>

#define B_  16
#define C_  256
#define IC_ 32
#define M_  16384
#define TM_ 128
#define TILES_ (M_/TM_)            // 128
#define RSQRT_IC 0.17677669529663687f

// ---------------- scratch (__device__ globals; no allocation allowed) -------
__device__ float d_g[(size_t)B_*IC_*M_];               // 33.5 MB  g_x (biased)
__device__ float d_partG[(size_t)B_*TILES_*IC_*IC_];   // per-tile t.t^T
__device__ float d_partS[(size_t)B_*TILES_*IC_];       // per-tile sum(t)
__device__ float d_weff[(size_t)B_*IC_*C_];            // w_w @ attn  [j][c]
// weights pre-split to bf16 hi/lo, packed in mma.m16n8k16 B-fragment order:
//   ushort index = ((((ks*8 + nb)*32 + lane)*2 + r) << 1) | e
//   where ks=k>>4, kr=k&15, r=kr>>3, ct=(kr&7)>>1, e=kr&1, nb=n>>3, lane=(n&7)*4+ct
__device__ __align__(16) unsigned short d_Bhi[64*256];
__device__ __align__(16) unsigned short d_Blo[64*256];

// ---------------- bf16 mma (baseline PTX, sm_80+; HMMA on sm_103) -----------
__device__ __forceinline__ void mma_bf16(float* d, const uint32_t* a,
                                         uint32_t b0, uint32_t b1) {
    asm volatile(
        "mma.sync.aligned.m16n8k16.row.col.f32.bf16.bf16.f32 "
        "{%0,%1,%2,%3}, {%4,%5,%6,%7}, {%8,%9}, {%0,%1,%2,%3};"
        : "+f"(d[0]), "+f"(d[1]), "+f"(d[2]), "+f"(d[3])
        : "r"(a[0]), "r"(a[1]), "r"(a[2]), "r"(a[3]), "r"(b0), "r"(b1));
}

__device__ __forceinline__ void split_pack(float f0, float f1,
                                           uint32_t& hi, uint32_t& lo) {
    uint32_t b0 = __float_as_uint(f0), b1 = __float_as_uint(f1);
    hi = __byte_perm(b0, b1, 0x7632);                 // {hi16(f0), hi16(f1)}
    float l0 = f0 - __uint_as_float(b0 & 0xFFFF0000u);
    float l1 = f1 - __uint_as_float(b1 & 0xFFFF0000u);
    __nv_bfloat162 p = __floats2bfloat162_rn(l0, l1);
    lo = *reinterpret_cast<uint32_t*>(&p);
}

// ============================================================================
// k0: split weights to bf16 hi/lo in B-fragment layout.
//   rows (n) 0..31 = theta_w, 32..63 = g_w.
// ============================================================================
__global__ void k0_prep(const float* __restrict__ g_w, const float* __restrict__ theta_w)
{
    int idx = blockIdx.x * 256 + threadIdx.x;    // 0..16383
    int n = idx >> 8, k = idx & 255;
    float wv = (n < 32) ? theta_w[n * C_ + k] : g_w[(n - 32) * C_ + k];
    uint32_t bits = __float_as_uint(wv);
    unsigned short hi = (unsigned short)(bits >> 16);
    float hif = __uint_as_float(bits & 0xFFFF0000u);
    unsigned short lo = __bfloat16_as_ushort(__float2bfloat16(wv - hif));
    int ks = k >> 4, kr = k & 15;
    int r = kr >> 3, ct = (kr & 7) >> 1, e = kr & 1;
    int nb = n >> 3, lane = (n & 7) * 4 + ct;
    int us = ((((ks * 8 + nb) * 32 + lane) * 2 + r) << 1) | e;
    d_Bhi[us] = hi;
    d_Blo[us] = lo;
}

// ============================================================================
// k1: per (batch, 128-pixel tile): D[128 m][64 n] = X^T(128x256) @ W^T(256x64)
//   via bf16 hi/lo mma.sync. n 0..31 -> theta (smem, Gram), 32..63 -> g (gmem).
// ============================================================================
__global__ __launch_bounds__(256) void k1_proj(
    const float* __restrict__ x,
    const float* __restrict__ g_b, const float* __restrict__ theta_b)
{
    __shared__ __align__(16) float Xs[64 * 132];   // [c][m], pitch 132 words
    float* Ts = Xs;                                 // reused: t as [m][33]

    const int t = threadIdx.x;
    const int w = t >> 5, lane = t & 31;
    const int gr = lane >> 2, ct = lane & 3;
    const int tile = blockIdx.x, b = blockIdx.y;
    const int mbase = tile * TM_;
    const int m0 = 16 * w + gr;

    float acc[8][4];
#pragma unroll
    for (int i = 0; i < 8; i++)
#pragma unroll
        for (int j = 0; j < 4; j++) acc[i][j] = 0.f;

    const uint2* Bhi2 = (const uint2*)d_Bhi;
    const uint2* Blo2 = (const uint2*)d_Blo;

    for (int chunk = 0; chunk < 4; chunk++) {
        const int c0 = chunk * 64;
        // ---- stage x chunk [64 c][128 m] fp32 (coalesced float4)
        const float* xb = x + ((size_t)b * C_ + c0) * M_ + mbase;
#pragma unroll
        for (int kk = 0; kk < 8; kk++) {
            int f = t + kk * 256;                 // 0..2047 float4s
            int cc = f >> 5, m4 = (f & 31) * 4;
            *(float4*)(Xs + cc * 132 + m4) =
                *(const float4*)(xb + (size_t)cc * M_ + m4);
        }
        __syncthreads();

#pragma unroll
        for (int ks = 0; ks < 4; ks++) {
            const int kb = ks * 16 + 2 * ct;
            // ---- A fragment (conflict-free LDS), split to hi/lo
            float f00 = Xs[(kb + 0) * 132 + m0],     f01 = Xs[(kb + 1) * 132 + m0];
            float f10 = Xs[(kb + 0) * 132 + m0 + 8], f11 = Xs[(kb + 1) * 132 + m0 + 8];
            float f20 = Xs[(kb + 8) * 132 + m0],     f21 = Xs[(kb + 9) * 132 + m0];
            float f30 = Xs[(kb + 8) * 132 + m0 + 8], f31 = Xs[(kb + 9) * 132 + m0 + 8];
            uint32_t ahi[4], alo[4];
            split_pack(f00, f01, ahi[0], alo[0]);
            split_pack(f10, f11, ahi[1], alo[1]);
            split_pack(f20, f21, ahi[2], alo[2]);
            split_pack(f30, f31, ahi[3], alo[3]);

            const int ksg = chunk * 4 + ks;
#pragma unroll
            for (int nb = 0; nb < 8; nb++) {
                uint2 bh = __ldg(&Bhi2[(ksg * 8 + nb) * 32 + lane]);
                uint2 bl = __ldg(&Blo2[(ksg * 8 + nb) * 32 + lane]);
                mma_bf16(acc[nb], ahi, bh.x, bh.y);   // hh
                mma_bf16(acc[nb], ahi, bl.x, bl.y);   // hl
                mma_bf16(acc[nb], alo, bh.x, bh.y);   // lh
            }
        }
        __syncthreads();
    }

    // ---- epilogue: theta -> Ts (smem), g -> d_g (gmem, +bias)
#pragma unroll
    for (int nb = 0; nb < 4; nb++) {
        int n = nb * 8 + 2 * ct;
        float tb0 = __ldg(&theta_b[n]), tb1 = __ldg(&theta_b[n + 1]);
        Ts[m0 * 33 + n]           = acc[nb][0] + tb0;
        Ts[m0 * 33 + n + 1]       = acc[nb][1] + tb1;
        Ts[(m0 + 8) * 33 + n]     = acc[nb][2] + tb0;
        Ts[(m0 + 8) * 33 + n + 1] = acc[nb][3] + tb1;
    }
#pragma unroll
    for (int nb = 4; nb < 8; nb++) {
        int n = (nb - 4) * 8 + 2 * ct;
        float gb0 = __ldg(&g_b[n]), gb1 = __ldg(&g_b[n + 1]);
        float* p0 = d_g + ((size_t)b * IC_ + n) * M_ + mbase;
        float* p1 = d_g + ((size_t)b * IC_ + n + 1) * M_ + mbase;
        p0[m0]     = acc[nb][0] + gb0;
        p1[m0]     = acc[nb][1] + gb1;
        p0[m0 + 8] = acc[nb][2] + gb0;
        p1[m0 + 8] = acc[nb][3] + gb1;
    }
    __syncthreads();

    // ---- partial Gram: warp w -> rows 4w..4w+3, lane j -> column j
    {
        const int j = lane;
        float gac[4] = {0.f, 0.f, 0.f, 0.f};
        float sac = 0.f;
        for (int m = 0; m < TM_; m++) {
            float tj = Ts[m * 33 + j];
#pragma unroll
            for (int ii = 0; ii < 4; ii++)
                gac[ii] += Ts[m * 33 + w * 4 + ii] * tj;
            if (w == 0) sac += tj;
        }
        float* pG = d_partG + (size_t)(b * TILES_ + tile) * IC_ * IC_;
#pragma unroll
        for (int ii = 0; ii < 4; ii++)
            pG[(w * 4 + ii) * IC_ + j] = gac[ii];
        if (w == 0)
            d_partS[(size_t)(b * TILES_ + tile) * IC_ + j] = sac;
    }
}

// ============================================================================
// k2 (one block per batch): reduce partials, sigma, softmax, fold w_eff
// ============================================================================
__global__ __launch_bounds__(256) void k2_attn(const float* __restrict__ w_w)
{
    __shared__ float gram[IC_ * IC_];
    __shared__ float mu[IC_];
    __shared__ float attn[IC_ * IC_];
    const int t = threadIdx.x, b = blockIdx.x;

    for (int e = t; e < IC_ * IC_; e += 256) {
        float s = 0.f;
        const float* p = d_partG + (size_t)b * TILES_ * IC_ * IC_ + e;
        for (int tl = 0; tl < TILES_; tl++) s += p[(size_t)tl * IC_ * IC_];
        gram[e] = s;
    }
    if (t < IC_) {
        float s = 0.f;
        const float* p = d_partS + (size_t)b * TILES_ * IC_ + t;
        for (int tl = 0; tl < TILES_; tl++) s += p[tl * IC_];
        mu[t] = s * (1.0f / M_);
    }
    __syncthreads();

    if (t < IC_) {
        float row[IC_];
        float mx = -CUDART_INF_F;
#pragma unroll
        for (int jj = 0; jj < IC_; jj++) {
            float v = (gram[t * IC_ + jj] * (1.0f / M_) - mu[t] * mu[jj]) * RSQRT_IC;
            row[jj] = v; mx = fmaxf(mx, v);
        }
        float sum = 0.f;
#pragma unroll
        for (int jj = 0; jj < IC_; jj++) { row[jj] = __expf(row[jj] - mx); sum += row[jj]; }
        float inv = 1.0f / sum;
#pragma unroll
        for (int jj = 0; jj < IC_; jj++) attn[t * IC_ + jj] = row[jj] * inv;
    }
    __syncthreads();

    {   // thread t == channel c
        int c = t;
        float ww[IC_];
#pragma unroll
        for (int ii = 0; ii < IC_; ii++) ww[ii] = w_w[c * IC_ + ii];
#pragma unroll
        for (int jj = 0; jj < IC_; jj++) {
            float s = 0.f;
#pragma unroll
            for (int ii = 0; ii < IC_; ii++) s += ww[ii] * attn[ii * IC_ + jj];
            d_weff[((size_t)b * IC_ + jj) * C_ + c] = s;
        }
    }
}

// ============================================================================
// k3: out[b][c][m] = sum_j weff[j][c]*g[j][m] + w_b[c] + x[b][c][m]
// ============================================================================
__global__ __launch_bounds__(256) void k3_out(
    const float* __restrict__ x, const float* __restrict__ w_b,
    float* __restrict__ out)
{
    __shared__ __align__(16) float gs[IC_ * 128];  // [j][m]
    __shared__ __align__(16) float wT[IC_ * 64];   // [j][c]

    const int t = threadIdx.x;
    const int tile = blockIdx.x, cb = blockIdx.y, b = blockIdx.z;
    const int mbase = tile * TM_;
    const int cbase = cb * 64;

#pragma unroll
    for (int k = 0; k < 4; k++) {
        int f = t + k * 256;
        int i = f >> 5, m4 = (f & 31) * 4;
        *(float4*)(gs + i * 128 + m4) =
            *(const float4*)(d_g + ((size_t)b * IC_ + i) * M_ + mbase + m4);
    }
#pragma unroll
    for (int k = 0; k < 8; k++) {
        int f = t + k * 256;
        int i = f >> 6, c = f & 63;
        wT[i * 64 + c] = d_weff[((size_t)b * IC_ + i) * C_ + cbase + c];
    }
    __syncthreads();

    const int c0 = (t >> 5) * 8, m0 = (t & 31) * 4;
    float acc[8][4];
#pragma unroll
    for (int i = 0; i < 8; i++)
#pragma unroll
        for (int j = 0; j < 4; j++) acc[i][j] = 0.f;

#pragma unroll
    for (int i = 0; i < IC_; i++) {
        float4 gv = *(const float4*)(gs + i * 128 + m0);
#pragma unroll
        for (int ii = 0; ii < 8; ii++) {
            float w = wT[i * 64 + c0 + ii];
            acc[ii][0] += w * gv.x; acc[ii][1] += w * gv.y;
            acc[ii][2] += w * gv.z; acc[ii][3] += w * gv.w;
        }
    }

    const size_t base = ((size_t)b * C_ + cbase + c0) * M_ + mbase + m0;
#pragma unroll
    for (int ii = 0; ii < 8; ii++) {
        float wb = w_b[cbase + c0 + ii];
        float4 xv = *(const float4*)(x + base + (size_t)ii * M_);
        float4 o = make_float4(acc[ii][0] + wb + xv.x, acc[ii][1] + wb + xv.y,
                               acc[ii][2] + wb + xv.z, acc[ii][3] + wb + xv.w);
        *(float4*)(out + base + (size_t)ii * M_) = o;
    }
}

// ============================================================================
extern "C" void kernel_launch(void* const* d_in, const int* in_sizes, int n_in,
                              void* d_out, int out_size)
{
    const float* x       = (const float*)d_in[0];
    const float* g_w     = (const float*)d_in[1];
    const float* g_b     = (const float*)d_in[2];
    const float* theta_w = (const float*)d_in[3];
    const float* theta_b = (const float*)d_in[4];
    const float* w_w     = (const float*)d_in[5];
    const float* w_b     = (const float*)d_in[6];
    float* out = (float*)d_out;

    k0_prep<<<64, 256>>>(g_w, theta_w);
    k1_proj<<<dim3(TILES_, B_), 256>>>(x, g_b, theta_b);
    k2_attn<<<B_, 256>>>(w_w);
    k3_out<<<dim3(TILES_, 4, B_), 256>>>(x, w_b, out);
}